// round 17
// baseline (speedup 1.0000x reference)
#include <cuda_runtime.h>

// Problem constants
#define GRID_M     96
#define NUM_NODES  9216          // 96*96
#define MAX_EDGES  36864         // 4*NUM_NODES
#define IMG_W      192
#define MASK_ELEMS 84934656      // 9216*9216
#define NBLK       36            // 36 blocks x 256 threads; all co-resident
#define NSLOT      288           // 36 blocks * 8 warps: one slot per warp

typedef unsigned long long u64;

// Scratch (no allocations, no resets, no atomics, no block barriers):
// One 64-bit slot per WARP, written exactly once per call by its owning warp.
// Tag = (own slot's previous high word + 1) << 32; all warps agree (each slot
// is bumped exactly once per call). Stale values are self-identifying.
__device__ u64 g_pub_min[NSLOT];  // tag | float_bits(warp min of pooled v)
__device__ u64 g_pub_max[NSLOT];  // tag | float_bits(warp max of pooled v)
__device__ u64 g_pub_cnt[NSLOT];  // tag | warp edge count

__device__ __forceinline__ u64 vload64(const u64* p) {
    return *((volatile const u64*)p);
}

// pool+noise value of node (i,j): bit-identical everywhere (same op order).
__device__ __forceinline__ float node_d(const float* __restrict__ dc,
                                        const float* __restrict__ noise,
                                        int i, int j) {
    const float2* r0 = reinterpret_cast<const float2*>(dc + (2 * i) * IMG_W);
    const float2* r1 = reinterpret_cast<const float2*>(dc + (2 * i + 1) * IMG_W);
    float2 a = r0[j];
    float2 c = r1[j];
    return fmaxf(fmaxf(a.x, a.y), fmaxf(c.x, c.y)) + noise[i * GRID_M + j];
}

// --------------------------------------------------------------------------
// Warp-autonomous fused kernel: 36 blocks x 256 threads, one node per thread.
// No __syncthreads, no shared memory on the critical path: every warp
// publishes its partials to L2 slots and polls all 288 slots itself.
// Global edge order = slot index asc -> lane asc -> neighbor-col asc
//                   = exact jnp.nonzero enumeration.
// --------------------------------------------------------------------------
__global__ __launch_bounds__(256, 1)
void k_fused(const float* __restrict__ dc, const float* __restrict__ noise,
             const unsigned int* __restrict__ mask, float* __restrict__ out) {
    const int b    = blockIdx.x;
    const int t    = threadIdx.x;
    const int lane = t & 31;
    const int w    = t >> 5;
    const int slot = b * 8 + w;            // this warp's slot, 0..287
    const int l    = b * 256 + t;          // node id, 0..9215
    const int i    = l / GRID_M;
    const int j    = l - i * GRID_M;

    // ---- per-call tag from this warp's OWN previous publication ----
    u64 prev = 0;
    if (lane == 0) prev = vload64(&g_pub_min[slot]);
    prev = __shfl_sync(0xffffffffu, prev, 0);
    const u64 tag = ((prev >> 32) + 1ull) << 32;

    // ---- Issue ALL independent scattered loads up front ----
    const bool up = (i > 0), dn = (i < GRID_M - 1);
    const bool lt = (j > 0), rt = (j < GRID_M - 1);
    const unsigned rowbase = (unsigned)l * (unsigned)NUM_NODES;

    unsigned mk0 = 0, mk1 = 0, mk2 = 0, mk3 = 0;   // dropout words (0/1)
    if (up && lt) mk0 = mask[rowbase + (unsigned)(l - 97)];
    if (up && rt) mk1 = mask[rowbase + (unsigned)(l - 95)];
    if (dn && lt) mk2 = mask[rowbase + (unsigned)(l + 95)];
    if (dn && rt) mk3 = mask[rowbase + (unsigned)(l + 97)];

    // own pooled value (pre-noise) + d
    float v;
    {
        const float2* r0 = reinterpret_cast<const float2*>(dc + (2 * i) * IMG_W);
        const float2* r1 = reinterpret_cast<const float2*>(dc + (2 * i + 1) * IMG_W);
        float2 a = r0[j];
        float2 c = r1[j];
        v = fmaxf(fmaxf(a.x, a.y), fmaxf(c.x, c.y));
    }
    const float dv = v + noise[l];

    // neighbor d values (bit-identical recomputation)
    float n0 = 0.f, n1 = 0.f, n2 = 0.f, n3 = 0.f;
    if (up && lt) n0 = node_d(dc, noise, i - 1, j - 1);
    if (up && rt) n1 = node_d(dc, noise, i - 1, j + 1);
    if (dn && lt) n2 = node_d(dc, noise, i + 1, j - 1);
    if (dn && rt) n3 = node_d(dc, noise, i + 1, j + 1);

    // ---- Sentinel fill (73728 floats = 2 x float4 per thread) ----
    {
        float4 s4 = make_float4((float)NUM_NODES, (float)NUM_NODES,
                                (float)NUM_NODES, (float)NUM_NODES);
        float4* o4 = reinterpret_cast<float4*>(out);
        o4[l]             = s4;
        o4[l + NUM_NODES] = s4;
    }

    // ---- Warp min/max of own 32 pooled values -> publish immediately ----
    {
        float mn = v, mx = v;
#pragma unroll
        for (int o = 16; o; o >>= 1) {
            mn = fminf(mn, __shfl_xor_sync(0xffffffffu, mn, o));
            mx = fmaxf(mx, __shfl_xor_sync(0xffffffffu, mx, o));
        }
        if (lane == 0) {
            g_pub_min[slot] = tag | (u64)(unsigned)__float_as_int(mn);
            g_pub_max[slot] = tag | (u64)(unsigned)__float_as_int(mx);
        }
    }

    // ---- Poll all 288 min/max slots (9 each per lane); payload = data ----
    float th;
    {
        u64 amn[9], amx[9];
        for (;;) {
            bool ok = true;
#pragma unroll
            for (int s = 0; s < 9; s++) {
                amn[s] = vload64(&g_pub_min[lane + 32 * s]);
                amx[s] = vload64(&g_pub_max[lane + 32 * s]);
                ok &= (amn[s] >= tag) & (amx[s] >= tag);
            }
            if (__all_sync(0xffffffffu, ok)) break;
        }
        float mn = __int_as_float((int)(unsigned)amn[0]);
        float mx = __int_as_float((int)(unsigned)amx[0]);
#pragma unroll
        for (int s = 1; s < 9; s++) {
            mn = fminf(mn, __int_as_float((int)(unsigned)amn[s]));
            mx = fmaxf(mx, __int_as_float((int)(unsigned)amx[s]));
        }
#pragma unroll
        for (int o = 16; o; o >>= 1) {
            mn = fminf(mn, __shfl_xor_sync(0xffffffffu, mn, o));
            mx = fmaxf(mx, __shfl_xor_sync(0xffffffffu, mx, o));
        }
        th = (mx - mn) / 96.0f;            // exact f32 op order as reference
    }

    // ---- Edge tests (all operands in registers) ----
    unsigned m = 0;
    if (mk0 && fabsf(n0 - dv) <= th) m |= 1u;   // (i-1,j-1)
    if (mk1 && fabsf(n1 - dv) <= th) m |= 2u;   // (i-1,j+1)
    if (mk2 && fabsf(n2 - dv) <= th) m |= 4u;   // (i+1,j-1)
    if (mk3 && fabsf(n3 - dv) <= th) m |= 8u;   // (i+1,j+1)

    // ---- Warp scan of per-thread counts; publish warp total ----
    const int c = __popc(m);
    int incl = c;
#pragma unroll
    for (int o = 1; o < 32; o <<= 1) {
        int u = __shfl_up_sync(0xffffffffu, incl, o);
        if (lane >= o) incl += u;
    }
    const int wtotal = __shfl_sync(0xffffffffu, incl, 31);
    if (lane == 0) g_pub_cnt[slot] = tag | (u64)(unsigned)wtotal;

    // ---- Poll all 288 count slots; compute this warp's global base ----
    int base;
    {
        u64 ac[9];
        for (;;) {
            bool ok = true;
#pragma unroll
            for (int s = 0; s < 9; s++) {
                ac[s] = vload64(&g_pub_cnt[lane + 32 * s]);
                ok &= (ac[s] >= tag);
            }
            if (__all_sync(0xffffffffu, ok)) break;
        }
        int sum = 0;
#pragma unroll
        for (int s = 0; s < 9; s++) {
            int idx = lane + 32 * s;
            sum += (idx < slot) ? (int)(unsigned)ac[s] : 0;
        }
#pragma unroll
        for (int o = 16; o; o >>= 1) sum += __shfl_xor_sync(0xffffffffu, sum, o);
        base = sum;
    }

    // ---- Scatter (jnp.nonzero order) over pre-written sentinels ----
    int pos = base + (incl - c);
    const float fl = (float)l;
    if (m & 1u) { out[pos] = fl; out[MAX_EDGES + pos] = (float)(l - 97); pos++; }
    if (m & 2u) { out[pos] = fl; out[MAX_EDGES + pos] = (float)(l - 95); pos++; }
    if (m & 4u) { out[pos] = fl; out[MAX_EDGES + pos] = (float)(l + 95); pos++; }
    if (m & 8u) { out[pos] = fl; out[MAX_EDGES + pos] = (float)(l + 97); pos++; }
}

// --------------------------------------------------------------------------
extern "C" void kernel_launch(void* const* d_in, const int* in_sizes, int n_in,
                              void* d_out, int out_size) {
    // Resolve inputs by element count (unique per input):
    //   d_coarse = 36864 (f32), noise = 9216 (f32),
    //   dropout_mask = 84934656 (bool materialized as 4-byte 0/1 words),
    //   R_scale = 1 (unused)
    const float*        dc    = nullptr;
    const float*        noise = nullptr;
    const unsigned int* mask  = nullptr;

    for (int i = 0; i < n_in; i++) {
        int s = in_sizes[i];
        if (s == MASK_ELEMS) mask  = (const unsigned int*)d_in[i];
        else if (s == 36864) dc    = (const float*)d_in[i];
        else if (s == 9216)  noise = (const float*)d_in[i];
    }

    float* out = (float*)d_out;   // [2, 36864] compared as float32

    k_fused<<<NBLK, 256>>>(dc, noise, mask, out);
}